// round 11
// baseline (speedup 1.0000x reference)
#include <cuda_runtime.h>
#include <cuda_fp16.h>
#include <cstdint>

// ---------------- problem constants ----------------
#define NTOT   8192
#define BHALF  4096
#define DD     256
#define TILE   128
#define KC     64       // K-chunk halves = 128 B/row (swizzle atom)
#define NCHUNK 4        // 256 / 64
#define NT     256      // 8 warps, 2x4 warp grid
#define NTILES 64
#define NBLK   (NTILES * (NTILES + 1) / 2)   // 2080
#define NCONV  (NTOT / 8)                    // 1024 convert blocks

// smem: [A0 16K][B0 16K][A1 16K][B1 16K][sq 1K][red 32B]
#define STAGE_BYTES 32768u
#define B_OFF       16384u
#define SQ_OFF      65536u
#define RED_OFF     66560u
#define SMEM_TOTAL  66624

// ---------------- device scratch ----------------
__device__ __half   g_x[NTOT * DD];
__device__ float    g_sq[NTOT];
__device__ float    g_sqpart[NCONV];
__device__ float    g_colpart[NCONV * DD];   // per-block column partials (no atomics)
__device__ float    g_m;
__device__ double   g_acc;
__device__ unsigned g_cnt1;          // zero-init; self-resetting
__device__ unsigned g_cnt2;

// ---------------- helpers ----------------
__device__ __forceinline__ uint32_t smem_u32(const void* p) {
    uint32_t a;
    asm("{ .reg .u64 t; cvta.to.shared.u64 t, %1; cvt.u32.u64 %0, t; }"
        : "=r"(a) : "l"(p));
    return a;
}
__device__ __forceinline__ void ldsm_x4(uint32_t& r0, uint32_t& r1,
                                        uint32_t& r2, uint32_t& r3,
                                        uint32_t addr) {
    asm volatile("ldmatrix.sync.aligned.m8n8.x4.shared.b16 {%0,%1,%2,%3}, [%4];"
                 : "=r"(r0), "=r"(r1), "=r"(r2), "=r"(r3) : "r"(addr));
}
__device__ __forceinline__ void mma_f16acc(uint32_t* d, const uint32_t* a,
                                           uint32_t b0, uint32_t b1) {
    asm volatile(
        "mma.sync.aligned.m16n8k16.row.col.f16.f16.f16.f16 "
        "{%0,%1}, {%2,%3,%4,%5}, {%6,%7}, {%0,%1};"
        : "+r"(d[0]), "+r"(d[1])
        : "r"(a[0]), "r"(a[1]), "r"(a[2]), "r"(a[3]), "r"(b0), "r"(b1));
}

// ---------------- prep: fp16 round + row norms + col partials + fused bw ----------------
__global__ void convert_kernel(const float* __restrict__ xs,
                               const float* __restrict__ xt) {
    int wid = threadIdx.x >> 5, lane = threadIdx.x & 31;
    int bid = blockIdx.x;
    int row = bid * 8 + wid;
    const float* p = (row < BHALF) ? xs + (size_t)row * DD
                                   : xt + (size_t)(row - BHALF) * DD;
    __half* q = g_x + (size_t)row * DD;

    __shared__ float scol2[8 * DD];      // [warp][column] rounded values

    int c0 = lane * 8;
    float4 v0 = *(const float4*)(p + c0);
    float4 v1 = *(const float4*)(p + c0 + 4);
    float f[8] = {v0.x, v0.y, v0.z, v0.w, v1.x, v1.y, v1.z, v1.w};
    float s = 0.f;
    half2* q2 = (half2*)(q + c0);
    #pragma unroll
    for (int j = 0; j < 4; j++) {
        __half h0 = __float2half_rn(f[2 * j]);
        __half h1 = __float2half_rn(f[2 * j + 1]);
        q2[j] = __halves2half2(h0, h1);
        float t0 = __half2float(h0), t1 = __half2float(h1);
        s = fmaf(t0, t0, s); s = fmaf(t1, t1, s);
        scol2[wid * DD + c0 + 2 * j]     = t0;
        scol2[wid * DD + c0 + 2 * j + 1] = t1;
    }
    #pragma unroll
    for (int o = 16; o; o >>= 1) s += __shfl_xor_sync(0xffffffffu, s, o);
    __shared__ float ws[8];
    if (lane == 0) { ws[wid] = s; g_sq[row] = s; }
    __syncthreads();

    // column partial over this block's 8 rows (exclusive slice, no atomics)
    {
        float cp = 0.f;
        #pragma unroll
        for (int w = 0; w < 8; w++) cp += scol2[w * DD + threadIdx.x];
        g_colpart[bid * DD + threadIdx.x] = cp;
    }
    if (threadIdx.x == 0) {
        float b = 0.f;
        #pragma unroll
        for (int w = 0; w < 8; w++) b += ws[w];
        g_sqpart[bid] = b;
    }

    // ---- fused bandwidth in the LAST convert block ----
    __shared__ int s_last;
    __threadfence();
    __syncthreads();
    if (threadIdx.x == 0)
        s_last = (atomicAdd(&g_cnt1, 1u) == (unsigned)NCONV - 1u);
    __syncthreads();
    if (!s_last) return;

    int t = threadIdx.x;
    float cs = 0.f;
    #pragma unroll 8
    for (int b2 = 0; b2 < NCONV; b2++) cs += g_colpart[b2 * DD + t];
    float sq = 0.f;
    #pragma unroll
    for (int i = 0; i < 4; i++) sq += g_sqpart[t + 256 * i];

    __shared__ double sh[256];
    sh[t] = (double)cs * (double)cs;
    __syncthreads();
    for (int s2 = 128; s2; s2 >>= 1) { if (t < s2) sh[t] += sh[t + s2]; __syncthreads(); }
    double cs_tot = sh[0];
    __syncthreads();
    sh[t] = (double)sq;
    __syncthreads();
    for (int s2 = 128; s2; s2 >>= 1) { if (t < s2) sh[t] += sh[t + s2]; __syncthreads(); }
    if (t == 0) {
        double sumsq = sh[0];
        double n = (double)NTOT;
        double sumL2 = 2.0 * n * sumsq - 2.0 * cs_tot;
        double bw = sumL2 / (n * n - n) / 4.0;
        g_m = (float)(1.4426950408889634 / (bw * 16.0));
        g_acc = 0.0;
        g_cnt1 = 0u;
    }
}

// ---------------- chunk loader: 2048 x 16B, 8 per thread ----------------
__device__ __forceinline__ void load_chunk(uint32_t sb, int buf,
                                           const __half* gA, const __half* gB,
                                           int k0, int tid) {
    uint32_t aB = sb + buf * STAGE_BYTES;
    uint32_t bB = aB + B_OFF;
    #pragma unroll
    for (int i = 0; i < 4; i++) {
        int u = tid + i * 256;
        int row = u >> 3, c = u & 7;
        uint32_t off = (uint32_t)(row * 128 + c * 16);
        uint32_t sw = off ^ ((off >> 3) & 0x70);
        const __half* srcA = gA + (size_t)row * DD + k0 + c * 8;
        const __half* srcB = gB + (size_t)row * DD + k0 + c * 8;
        asm volatile("cp.async.cg.shared.global [%0], [%1], 16;"
                     :: "r"(aB + sw), "l"(srcA));
        asm volatile("cp.async.cg.shared.global [%0], [%1], 16;"
                     :: "r"(bB + sw), "l"(srcB));
    }
    asm volatile("cp.async.commit_group;" ::: "memory");
}

// ---------------- main tensor-core kernel (EXACT round-7 body) ----------------
__global__ void __launch_bounds__(NT, 3) mmd_mma_kernel(float* __restrict__ out) {
    int b = blockIdx.x;
    int ti = (int)((sqrtf(8.f * (float)b + 1.f) - 1.f) * 0.5f);
    while ((ti + 1) * (ti + 2) / 2 <= b) ti++;
    while (ti * (ti + 1) / 2 > b) ti--;
    int tj = b - ti * (ti + 1) / 2;

    extern __shared__ char smem[];
    uint32_t sb = smem_u32(smem);
    int tid = threadIdx.x, wid = tid >> 5, lane = tid & 31;

    const __half* gA = g_x + (size_t)ti * TILE * DD;
    const __half* gB = g_x + (size_t)tj * TILE * DD;

    load_chunk(sb, 0, gA, gB, 0, tid);

    // stage sq slices for the epilogue
    float* sqrow = (float*)(smem + SQ_OFF);          // 128
    float* sqcol = sqrow + TILE;                     // 128
    if (tid < TILE) sqrow[tid] = g_sq[ti * TILE + tid];
    else            sqcol[tid - TILE] = g_sq[tj * TILE + (tid - TILE)];

    int wm = (wid >> 2) * 64;
    int wn = (wid & 3) * 32;

    uint32_t acc[4][4][2];
    #pragma unroll
    for (int a = 0; a < 4; a++)
        #pragma unroll
        for (int c = 0; c < 4; c++) { acc[a][c][0] = 0u; acc[a][c][1] = 0u; }

    int grp = lane >> 3, rin = lane & 7;
    int aRow = wm + (grp & 1) * 8 + rin;
    int aKB  = (grp >> 1) * 16;
    int bRow = wn + (grp >> 1) * 8 + rin;
    int bKB  = (grp & 1) * 16;
    uint32_t aMask = (uint32_t)((aRow & 7) << 4);
    uint32_t bMask = (uint32_t)((bRow & 7) << 4);

    for (int ck = 0; ck < NCHUNK; ck++) {
        if (ck < NCHUNK - 1) {
            load_chunk(sb, (ck + 1) & 1, gA, gB, (ck + 1) * KC, tid);
            asm volatile("cp.async.wait_group 1;" ::: "memory");
        } else {
            asm volatile("cp.async.wait_group 0;" ::: "memory");
        }
        __syncthreads();

        uint32_t aB = sb + (uint32_t)(ck & 1) * STAGE_BYTES;
        uint32_t bB = aB + B_OFF;

        #pragma unroll
        for (int ks = 0; ks < 4; ks++) {
            uint32_t a[4][4], bf[2][4];
            #pragma unroll
            for (int mt = 0; mt < 4; mt++) {
                uint32_t addr = aB + (uint32_t)((aRow + mt * 16) * 128)
                              + (((uint32_t)(ks * 32 + aKB)) ^ aMask);
                ldsm_x4(a[mt][0], a[mt][1], a[mt][2], a[mt][3], addr);
            }
            #pragma unroll
            for (int nh = 0; nh < 2; nh++) {
                uint32_t addr = bB + (uint32_t)((bRow + nh * 16) * 128)
                              + (((uint32_t)(ks * 32 + bKB)) ^ bMask);
                ldsm_x4(bf[nh][0], bf[nh][1], bf[nh][2], bf[nh][3], addr);
            }
            #pragma unroll
            for (int mt = 0; mt < 4; mt++)
                #pragma unroll
                for (int nt = 0; nt < 4; nt++)
                    mma_f16acc(acc[mt][nt], a[mt],
                               bf[nt >> 1][(nt & 1) * 2],
                               bf[nt >> 1][(nt & 1) * 2 + 1]);
        }
        __syncthreads();
    }

    // ---- epilogue: L2 -> 5-kernel RBF sum ----
    float m = g_m;
    int rbase = wm + (lane >> 2);
    int cbase = wn + ((lane & 3) << 1);
    int rglob = ti * TILE, cglob = tj * TILE;
    float total = 0.f;
    #pragma unroll
    for (int mt = 0; mt < 4; mt++) {
        int rr = rbase + mt * 16;
        #pragma unroll
        for (int nt = 0; nt < 4; nt++) {
            int cc = cbase + nt * 8;
            float sb0 = sqcol[cc], sb1 = sqcol[cc + 1];
            #pragma unroll
            for (int e2 = 0; e2 < 2; e2++) {
                int rl = rr + e2 * 8;
                float sa = sqrow[rl];
                float2 dv = __half22float2(*(const half2*)&acc[mt][nt][e2]);
                float L2a = fmaxf(sa + sb0 - 2.f * dv.x, 0.f);
                float L2b = fmaxf(sa + sb1 - 2.f * dv.y, 0.f);
                float ea, eb;
                asm("ex2.approx.ftz.f32 %0, %1;" : "=f"(ea) : "f"(-L2a * m));
                asm("ex2.approx.ftz.f32 %0, %1;" : "=f"(eb) : "f"(-L2b * m));
                float ea1 = ea * ea, ea2 = ea1 * ea1, ea3 = ea2 * ea2, ea4 = ea3 * ea3;
                float eb1 = eb * eb, eb2 = eb1 * eb1, eb3 = eb2 * eb2, eb4 = eb3 * eb3;
                float kva = ((ea + ea1) + (ea2 + ea3)) + ea4;
                float kvb = ((eb + eb1) + (eb2 + eb3)) + eb4;
                int rg = rglob + rl, cg = cglob + cc;
                total += (rg > cg)     ? kva : 0.f;
                total += (rg > cg + 1) ? kvb : 0.f;
            }
        }
    }
    total *= (((ti < 32) == (tj < 32)) ? 2.f : -2.f);

    #pragma unroll
    for (int o = 16; o; o >>= 1) total += __shfl_xor_sync(0xffffffffu, total, o);
    float* red = (float*)(smem + RED_OFF);
    if (lane == 0) red[wid] = total;
    __syncthreads();
    if (tid == 0) {
        float s = 0.f;
        #pragma unroll
        for (int w = 0; w < 8; w++) s += red[w];
        atomicAdd(&g_acc, (double)s);
        __threadfence();
        if (atomicAdd(&g_cnt2, 1u) == (unsigned)NBLK - 1u) {
            out[0] = (float)((g_acc + (double)NTOT * 5.0) /
                             ((double)BHALF * (double)BHALF));
            g_cnt2 = 0u;
        }
    }
}

// ---------------- launch ----------------
extern "C" void kernel_launch(void* const* d_in, const int* in_sizes, int n_in,
                              void* d_out, int out_size) {
    const float* xs = (const float*)d_in[0];
    const float* xt = (const float*)d_in[1];
    float* out = (float*)d_out;

    cudaFuncSetAttribute(mmd_mma_kernel,
                         cudaFuncAttributeMaxDynamicSharedMemorySize, SMEM_TOTAL);

    convert_kernel<<<NCONV, 256>>>(xs, xt);
    mmd_mma_kernel<<<NBLK, NT, SMEM_TOTAL>>>(out);
}

// round 12
// speedup vs baseline: 1.2977x; 1.2977x over previous
#include <cuda_runtime.h>
#include <cuda_fp16.h>
#include <cstdint>

// ---------------- problem constants ----------------
#define NTOT   8192
#define BHALF  4096
#define DD     256
#define TILE   128
#define KC     64       // K-chunk halves = 128 B/row (swizzle atom)
#define NCHUNK 4        // 256 / 64
#define NT     256      // 8 warps, 2x4 warp grid
#define NTILES 64
#define NBLK   (NTILES * (NTILES + 1) / 2)   // 2080

// smem: [A0 16K][B0 16K][A1 16K][B1 16K][sq 1K][red 32B]
#define STAGE_BYTES 32768u
#define B_OFF       16384u
#define SQ_OFF      65536u
#define RED_OFF     66560u
#define SMEM_TOTAL  66624

// ---------------- device scratch ----------------
__device__ __half   g_x[NTOT * DD];
__device__ float    g_sq[NTOT];
__device__ float    g_sqpart[1024];
__device__ float    g_colpart[32 * DD];
__device__ float    g_m;
__device__ double   g_acc;
__device__ unsigned g_cnt1;          // zero-init; self-resetting
__device__ unsigned g_cnt2;

// ---------------- helpers ----------------
__device__ __forceinline__ uint32_t smem_u32(const void* p) {
    uint32_t a;
    asm("{ .reg .u64 t; cvta.to.shared.u64 t, %1; cvt.u32.u64 %0, t; }"
        : "=r"(a) : "l"(p));
    return a;
}
__device__ __forceinline__ void ldsm_x4(uint32_t& r0, uint32_t& r1,
                                        uint32_t& r2, uint32_t& r3,
                                        uint32_t addr) {
    asm volatile("ldmatrix.sync.aligned.m8n8.x4.shared.b16 {%0,%1,%2,%3}, [%4];"
                 : "=r"(r0), "=r"(r1), "=r"(r2), "=r"(r3) : "r"(addr));
}
__device__ __forceinline__ void mma_f16acc(uint32_t* d, const uint32_t* a,
                                           uint32_t b0, uint32_t b1) {
    asm volatile(
        "mma.sync.aligned.m16n8k16.row.col.f16.f16.f16.f16 "
        "{%0,%1}, {%2,%3,%4,%5}, {%6,%7}, {%0,%1};"
        : "+r"(d[0]), "+r"(d[1])
        : "r"(a[0]), "r"(a[1]), "r"(a[2]), "r"(a[3]), "r"(b0), "r"(b1));
}

// ---------------- prep: round to fp16, row norms (round-7 proven) ----------------
__global__ void convert_kernel(const float* __restrict__ xs,
                               const float* __restrict__ xt) {
    int wid = threadIdx.x >> 5, lane = threadIdx.x & 31;
    int row = blockIdx.x * 8 + wid;
    const float* p = (row < BHALF) ? xs + (size_t)row * DD
                                   : xt + (size_t)(row - BHALF) * DD;
    __half* q = g_x + (size_t)row * DD;

    int c0 = lane * 8;
    float4 v0 = *(const float4*)(p + c0);
    float4 v1 = *(const float4*)(p + c0 + 4);
    float f[8] = {v0.x, v0.y, v0.z, v0.w, v1.x, v1.y, v1.z, v1.w};
    float s = 0.f;
    half2* q2 = (half2*)(q + c0);
    #pragma unroll
    for (int j = 0; j < 4; j++) {
        __half h0 = __float2half_rn(f[2 * j]);
        __half h1 = __float2half_rn(f[2 * j + 1]);
        q2[j] = __halves2half2(h0, h1);
        float t0 = __half2float(h0), t1 = __half2float(h1);
        s = fmaf(t0, t0, s); s = fmaf(t1, t1, s);
    }
    #pragma unroll
    for (int o = 16; o; o >>= 1) s += __shfl_xor_sync(0xffffffffu, s, o);
    __shared__ float ws[8];
    if (lane == 0) { ws[wid] = s; g_sq[row] = s; }
    __syncthreads();
    if (threadIdx.x == 0) {
        float b = 0.f;
        #pragma unroll
        for (int w = 0; w < 8; w++) b += ws[w];
        g_sqpart[blockIdx.x] = b;
    }
}

// ---------------- colsum (32 blocks) + fused bandwidth in last block (round-7) ----------------
__global__ void colsum_bw_kernel() {
    int t = threadIdx.x;
    int r0 = blockIdx.x * 256;
    float s = 0.f;
    for (int r = r0; r < r0 + 256; r++)
        s += __half2float(g_x[(size_t)r * DD + t]);
    g_colpart[blockIdx.x * DD + t] = s;

    __shared__ int s_last;
    __threadfence();
    __syncthreads();
    if (t == 0) s_last = (atomicAdd(&g_cnt1, 1u) == 31u);
    __syncthreads();
    if (!s_last) return;

    __shared__ double sh[256];
    float cs = 0.f;
    #pragma unroll 4
    for (int b = 0; b < 32; b++) cs += g_colpart[b * DD + t];
    float sq = 0.f;
    #pragma unroll
    for (int i = 0; i < 4; i++) sq += g_sqpart[t + 256 * i];

    sh[t] = (double)cs * (double)cs;
    __syncthreads();
    for (int s2 = 128; s2; s2 >>= 1) { if (t < s2) sh[t] += sh[t + s2]; __syncthreads(); }
    double cs_tot = sh[0];
    __syncthreads();
    sh[t] = (double)sq;
    __syncthreads();
    for (int s2 = 128; s2; s2 >>= 1) { if (t < s2) sh[t] += sh[t + s2]; __syncthreads(); }
    if (t == 0) {
        double sumsq = sh[0];
        double n = (double)NTOT;
        double sumL2 = 2.0 * n * sumsq - 2.0 * cs_tot;
        double bw = sumL2 / (n * n - n) / 4.0;
        g_m = (float)(1.4426950408889634 / (bw * 16.0));
        g_acc = 0.0;
        g_cnt1 = 0u;
    }
}

// ---------------- chunk loader: 2048 x 16B, 8 per thread ----------------
__device__ __forceinline__ void load_chunk(uint32_t sb, int buf,
                                           const __half* gA, const __half* gB,
                                           int k0, int tid) {
    uint32_t aB = sb + buf * STAGE_BYTES;
    uint32_t bB = aB + B_OFF;
    #pragma unroll
    for (int i = 0; i < 4; i++) {
        int u = tid + i * 256;
        int row = u >> 3, c = u & 7;
        uint32_t off = (uint32_t)(row * 128 + c * 16);
        uint32_t sw = off ^ ((off >> 3) & 0x70);
        const __half* srcA = gA + (size_t)row * DD + k0 + c * 8;
        const __half* srcB = gB + (size_t)row * DD + k0 + c * 8;
        asm volatile("cp.async.cg.shared.global [%0], [%1], 16;"
                     :: "r"(aB + sw), "l"(srcA));
        asm volatile("cp.async.cg.shared.global [%0], [%1], 16;"
                     :: "r"(bB + sw), "l"(srcB));
    }
    asm volatile("cp.async.commit_group;" ::: "memory");
}

// ---------------- main tensor-core kernel (EXACT round-11 body, 58.7us) ----------------
__global__ void __launch_bounds__(NT, 3) mmd_mma_kernel(float* __restrict__ out) {
    int b = blockIdx.x;
    int ti = (int)((sqrtf(8.f * (float)b + 1.f) - 1.f) * 0.5f);
    while ((ti + 1) * (ti + 2) / 2 <= b) ti++;
    while (ti * (ti + 1) / 2 > b) ti--;
    int tj = b - ti * (ti + 1) / 2;

    extern __shared__ char smem[];
    uint32_t sb = smem_u32(smem);
    int tid = threadIdx.x, wid = tid >> 5, lane = tid & 31;

    const __half* gA = g_x + (size_t)ti * TILE * DD;
    const __half* gB = g_x + (size_t)tj * TILE * DD;

    load_chunk(sb, 0, gA, gB, 0, tid);

    // stage sq slices for the epilogue
    float* sqrow = (float*)(smem + SQ_OFF);          // 128
    float* sqcol = sqrow + TILE;                     // 128
    if (tid < TILE) sqrow[tid] = g_sq[ti * TILE + tid];
    else            sqcol[tid - TILE] = g_sq[tj * TILE + (tid - TILE)];

    int wm = (wid >> 2) * 64;
    int wn = (wid & 3) * 32;

    uint32_t acc[4][4][2];
    #pragma unroll
    for (int a = 0; a < 4; a++)
        #pragma unroll
        for (int c = 0; c < 4; c++) { acc[a][c][0] = 0u; acc[a][c][1] = 0u; }

    int grp = lane >> 3, rin = lane & 7;
    int aRow = wm + (grp & 1) * 8 + rin;
    int aKB  = (grp >> 1) * 16;
    int bRow = wn + (grp >> 1) * 8 + rin;
    int bKB  = (grp & 1) * 16;
    uint32_t aMask = (uint32_t)((aRow & 7) << 4);
    uint32_t bMask = (uint32_t)((bRow & 7) << 4);

    for (int ck = 0; ck < NCHUNK; ck++) {
        if (ck < NCHUNK - 1) {
            load_chunk(sb, (ck + 1) & 1, gA, gB, (ck + 1) * KC, tid);
            asm volatile("cp.async.wait_group 1;" ::: "memory");
        } else {
            asm volatile("cp.async.wait_group 0;" ::: "memory");
        }
        __syncthreads();

        uint32_t aB = sb + (uint32_t)(ck & 1) * STAGE_BYTES;
        uint32_t bB = aB + B_OFF;

        #pragma unroll
        for (int ks = 0; ks < 4; ks++) {
            uint32_t a[4][4], bf[2][4];
            #pragma unroll
            for (int mt = 0; mt < 4; mt++) {
                uint32_t addr = aB + (uint32_t)((aRow + mt * 16) * 128)
                              + (((uint32_t)(ks * 32 + aKB)) ^ aMask);
                ldsm_x4(a[mt][0], a[mt][1], a[mt][2], a[mt][3], addr);
            }
            #pragma unroll
            for (int nh = 0; nh < 2; nh++) {
                uint32_t addr = bB + (uint32_t)((bRow + nh * 16) * 128)
                              + (((uint32_t)(ks * 32 + bKB)) ^ bMask);
                ldsm_x4(bf[nh][0], bf[nh][1], bf[nh][2], bf[nh][3], addr);
            }
            #pragma unroll
            for (int mt = 0; mt < 4; mt++)
                #pragma unroll
                for (int nt = 0; nt < 4; nt++)
                    mma_f16acc(acc[mt][nt], a[mt],
                               bf[nt >> 1][(nt & 1) * 2],
                               bf[nt >> 1][(nt & 1) * 2 + 1]);
        }
        __syncthreads();
    }

    // ---- epilogue: L2 -> 5-kernel RBF sum ----
    float m = g_m;
    int rbase = wm + (lane >> 2);
    int cbase = wn + ((lane & 3) << 1);
    int rglob = ti * TILE, cglob = tj * TILE;
    float total = 0.f;
    #pragma unroll
    for (int mt = 0; mt < 4; mt++) {
        int rr = rbase + mt * 16;
        #pragma unroll
        for (int nt = 0; nt < 4; nt++) {
            int cc = cbase + nt * 8;
            float sb0 = sqcol[cc], sb1 = sqcol[cc + 1];
            #pragma unroll
            for (int e2 = 0; e2 < 2; e2++) {
                int rl = rr + e2 * 8;
                float sa = sqrow[rl];
                float2 dv = __half22float2(*(const half2*)&acc[mt][nt][e2]);
                float L2a = fmaxf(sa + sb0 - 2.f * dv.x, 0.f);
                float L2b = fmaxf(sa + sb1 - 2.f * dv.y, 0.f);
                float ea, eb;
                asm("ex2.approx.ftz.f32 %0, %1;" : "=f"(ea) : "f"(-L2a * m));
                asm("ex2.approx.ftz.f32 %0, %1;" : "=f"(eb) : "f"(-L2b * m));
                float ea1 = ea * ea, ea2 = ea1 * ea1, ea3 = ea2 * ea2, ea4 = ea3 * ea3;
                float eb1 = eb * eb, eb2 = eb1 * eb1, eb3 = eb2 * eb2, eb4 = eb3 * eb3;
                float kva = ((ea + ea1) + (ea2 + ea3)) + ea4;
                float kvb = ((eb + eb1) + (eb2 + eb3)) + eb4;
                int rg = rglob + rl, cg = cglob + cc;
                total += (rg > cg)     ? kva : 0.f;
                total += (rg > cg + 1) ? kvb : 0.f;
            }
        }
    }
    total *= (((ti < 32) == (tj < 32)) ? 2.f : -2.f);

    #pragma unroll
    for (int o = 16; o; o >>= 1) total += __shfl_xor_sync(0xffffffffu, total, o);
    float* red = (float*)(smem + RED_OFF);
    if (lane == 0) red[wid] = total;
    __syncthreads();
    if (tid == 0) {
        float s = 0.f;
        #pragma unroll
        for (int w = 0; w < 8; w++) s += red[w];
        atomicAdd(&g_acc, (double)s);
        __threadfence();
        if (atomicAdd(&g_cnt2, 1u) == (unsigned)NBLK - 1u) {
            out[0] = (float)((g_acc + (double)NTOT * 5.0) /
                             ((double)BHALF * (double)BHALF));
            g_cnt2 = 0u;
        }
    }
}

// ---------------- launch ----------------
extern "C" void kernel_launch(void* const* d_in, const int* in_sizes, int n_in,
                              void* d_out, int out_size) {
    const float* xs = (const float*)d_in[0];
    const float* xt = (const float*)d_in[1];
    float* out = (float*)d_out;

    cudaFuncSetAttribute(mmd_mma_kernel,
                         cudaFuncAttributeMaxDynamicSharedMemorySize, SMEM_TOTAL);

    convert_kernel<<<NTOT / 8, 256>>>(xs, xt);
    colsum_bw_kernel<<<32, 256>>>();
    mmd_mma_kernel<<<NBLK, NT, SMEM_TOTAL>>>(out);
}

// round 13
// speedup vs baseline: 1.4452x; 1.1137x over previous
#include <cuda_runtime.h>
#include <cuda_fp16.h>
#include <cstdint>

// ---------------- problem constants ----------------
#define NTOT   8192
#define BHALF  4096
#define DD     256
#define TILE   128
#define KC     64       // K-chunk halves = 128 B/row (swizzle atom)
#define NCHUNK 4        // 256 / 64
#define NT     256      // 8 warps, 2x4 warp grid
#define NTILES 64
#define NBLK   (NTILES * (NTILES + 1) / 2)   // 2080
#define NCONV  (NTOT / 8)                    // 1024 convert blocks

// smem: [A0 16K][B0 16K][A1 16K][B1 16K][sq 1K][red 32B]
#define STAGE_BYTES 32768u
#define B_OFF       16384u
#define SQ_OFF      65536u
#define RED_OFF     66560u
#define SMEM_TOTAL  66624

// ---------------- device scratch ----------------
__device__ __half   g_x[NTOT * DD];
__device__ float    g_sq[NTOT];
__device__ float    g_sqpart[NCONV];
__device__ float    g_colpart[32 * DD];  // 32 slices; zero-init; reset by last block
__device__ float    g_m;
__device__ double   g_acc;
__device__ unsigned g_cnt1;          // zero-init; self-resetting
__device__ unsigned g_cnt2;

// ---------------- helpers ----------------
__device__ __forceinline__ uint32_t smem_u32(const void* p) {
    uint32_t a;
    asm("{ .reg .u64 t; cvta.to.shared.u64 t, %1; cvt.u32.u64 %0, t; }"
        : "=r"(a) : "l"(p));
    return a;
}
__device__ __forceinline__ void ldsm_x4(uint32_t& r0, uint32_t& r1,
                                        uint32_t& r2, uint32_t& r3,
                                        uint32_t addr) {
    asm volatile("ldmatrix.sync.aligned.m8n8.x4.shared.b16 {%0,%1,%2,%3}, [%4];"
                 : "=r"(r0), "=r"(r1), "=r"(r2), "=r"(r3) : "r"(addr));
}
__device__ __forceinline__ void mma_f16acc(uint32_t* d, const uint32_t* a,
                                           uint32_t b0, uint32_t b1) {
    asm volatile(
        "mma.sync.aligned.m16n8k16.row.col.f16.f16.f16.f16 "
        "{%0,%1}, {%2,%3,%4,%5}, {%6,%7}, {%0,%1};"
        : "+r"(d[0]), "+r"(d[1])
        : "r"(a[0]), "r"(a[1]), "r"(a[2]), "r"(a[3]), "r"(b0), "r"(b1));
}

// ---------------- prep: fp16 round + row norms + 32-slice col partials + bw ----------------
__global__ void convert_kernel(const float* __restrict__ xs,
                               const float* __restrict__ xt) {
    int wid = threadIdx.x >> 5, lane = threadIdx.x & 31;
    int bid = blockIdx.x;
    int row = bid * 8 + wid;
    const float* p = (row < BHALF) ? xs + (size_t)row * DD
                                   : xt + (size_t)(row - BHALF) * DD;
    __half* q = g_x + (size_t)row * DD;

    __shared__ float scol2[8 * DD];      // [warp][column] rounded values

    int c0 = lane * 8;
    float4 v0 = *(const float4*)(p + c0);
    float4 v1 = *(const float4*)(p + c0 + 4);
    float f[8] = {v0.x, v0.y, v0.z, v0.w, v1.x, v1.y, v1.z, v1.w};
    float s = 0.f;
    half2* q2 = (half2*)(q + c0);
    #pragma unroll
    for (int j = 0; j < 4; j++) {
        __half h0 = __float2half_rn(f[2 * j]);
        __half h1 = __float2half_rn(f[2 * j + 1]);
        q2[j] = __halves2half2(h0, h1);
        float t0 = __half2float(h0), t1 = __half2float(h1);
        s = fmaf(t0, t0, s); s = fmaf(t1, t1, s);
        scol2[wid * DD + c0 + 2 * j]     = t0;
        scol2[wid * DD + c0 + 2 * j + 1] = t1;
    }
    #pragma unroll
    for (int o = 16; o; o >>= 1) s += __shfl_xor_sync(0xffffffffu, s, o);
    __shared__ float ws[8];
    if (lane == 0) { ws[wid] = s; g_sq[row] = s; }
    __syncthreads();

    // per-block column partial -> one of 32 slices (32-way contention only)
    {
        float cp = 0.f;
        #pragma unroll
        for (int w = 0; w < 8; w++) cp += scol2[w * DD + threadIdx.x];
        atomicAdd(&g_colpart[(bid & 31) * DD + threadIdx.x], cp);
    }
    if (threadIdx.x == 0) {
        float b = 0.f;
        #pragma unroll
        for (int w = 0; w < 8; w++) b += ws[w];
        g_sqpart[bid] = b;
    }

    // ---- fused bandwidth in the LAST convert block (32x256 reduction only) ----
    __shared__ int s_last;
    __threadfence();
    __syncthreads();
    if (threadIdx.x == 0)
        s_last = (atomicAdd(&g_cnt1, 1u) == (unsigned)NCONV - 1u);
    __syncthreads();
    if (!s_last) return;

    int t = threadIdx.x;
    float cs = 0.f;
    #pragma unroll 4
    for (int b2 = 0; b2 < 32; b2++) cs += g_colpart[b2 * DD + t];
    float sq = 0.f;
    #pragma unroll
    for (int i = 0; i < 4; i++) sq += g_sqpart[t + 256 * i];

    __shared__ double sh[256];
    sh[t] = (double)cs * (double)cs;
    __syncthreads();
    for (int s2 = 128; s2; s2 >>= 1) { if (t < s2) sh[t] += sh[t + s2]; __syncthreads(); }
    double cs_tot = sh[0];
    __syncthreads();
    sh[t] = (double)sq;
    __syncthreads();
    for (int s2 = 128; s2; s2 >>= 1) { if (t < s2) sh[t] += sh[t + s2]; __syncthreads(); }
    // reset column slices for the next graph replay (after use)
    #pragma unroll 4
    for (int b2 = 0; b2 < 32; b2++) g_colpart[b2 * DD + t] = 0.f;
    if (t == 0) {
        double sumsq = sh[0];
        double n = (double)NTOT;
        double sumL2 = 2.0 * n * sumsq - 2.0 * cs_tot;
        double bw = sumL2 / (n * n - n) / 4.0;
        g_m = (float)(1.4426950408889634 / (bw * 16.0));
        g_acc = 0.0;
        g_cnt1 = 0u;
    }
}

// ---------------- chunk loader: 2048 x 16B, 8 per thread ----------------
__device__ __forceinline__ void load_chunk(uint32_t sb, int buf,
                                           const __half* gA, const __half* gB,
                                           int k0, int tid) {
    uint32_t aB = sb + buf * STAGE_BYTES;
    uint32_t bB = aB + B_OFF;
    #pragma unroll
    for (int i = 0; i < 4; i++) {
        int u = tid + i * 256;
        int row = u >> 3, c = u & 7;
        uint32_t off = (uint32_t)(row * 128 + c * 16);
        uint32_t sw = off ^ ((off >> 3) & 0x70);
        const __half* srcA = gA + (size_t)row * DD + k0 + c * 8;
        const __half* srcB = gB + (size_t)row * DD + k0 + c * 8;
        asm volatile("cp.async.cg.shared.global [%0], [%1], 16;"
                     :: "r"(aB + sw), "l"(srcA));
        asm volatile("cp.async.cg.shared.global [%0], [%1], 16;"
                     :: "r"(bB + sw), "l"(srcB));
    }
    asm volatile("cp.async.commit_group;" ::: "memory");
}

// ---------------- main tensor-core kernel (EXACT round-12 body, 58.7us) ----------------
__global__ void __launch_bounds__(NT, 3) mmd_mma_kernel(float* __restrict__ out) {
    int b = blockIdx.x;
    int ti = (int)((sqrtf(8.f * (float)b + 1.f) - 1.f) * 0.5f);
    while ((ti + 1) * (ti + 2) / 2 <= b) ti++;
    while (ti * (ti + 1) / 2 > b) ti--;
    int tj = b - ti * (ti + 1) / 2;

    extern __shared__ char smem[];
    uint32_t sb = smem_u32(smem);
    int tid = threadIdx.x, wid = tid >> 5, lane = tid & 31;

    const __half* gA = g_x + (size_t)ti * TILE * DD;
    const __half* gB = g_x + (size_t)tj * TILE * DD;

    load_chunk(sb, 0, gA, gB, 0, tid);

    // stage sq slices for the epilogue
    float* sqrow = (float*)(smem + SQ_OFF);          // 128
    float* sqcol = sqrow + TILE;                     // 128
    if (tid < TILE) sqrow[tid] = g_sq[ti * TILE + tid];
    else            sqcol[tid - TILE] = g_sq[tj * TILE + (tid - TILE)];

    int wm = (wid >> 2) * 64;
    int wn = (wid & 3) * 32;

    uint32_t acc[4][4][2];
    #pragma unroll
    for (int a = 0; a < 4; a++)
        #pragma unroll
        for (int c = 0; c < 4; c++) { acc[a][c][0] = 0u; acc[a][c][1] = 0u; }

    int grp = lane >> 3, rin = lane & 7;
    int aRow = wm + (grp & 1) * 8 + rin;
    int aKB  = (grp >> 1) * 16;
    int bRow = wn + (grp >> 1) * 8 + rin;
    int bKB  = (grp & 1) * 16;
    uint32_t aMask = (uint32_t)((aRow & 7) << 4);
    uint32_t bMask = (uint32_t)((bRow & 7) << 4);

    for (int ck = 0; ck < NCHUNK; ck++) {
        if (ck < NCHUNK - 1) {
            load_chunk(sb, (ck + 1) & 1, gA, gB, (ck + 1) * KC, tid);
            asm volatile("cp.async.wait_group 1;" ::: "memory");
        } else {
            asm volatile("cp.async.wait_group 0;" ::: "memory");
        }
        __syncthreads();

        uint32_t aB = sb + (uint32_t)(ck & 1) * STAGE_BYTES;
        uint32_t bB = aB + B_OFF;

        #pragma unroll
        for (int ks = 0; ks < 4; ks++) {
            uint32_t a[4][4], bf[2][4];
            #pragma unroll
            for (int mt = 0; mt < 4; mt++) {
                uint32_t addr = aB + (uint32_t)((aRow + mt * 16) * 128)
                              + (((uint32_t)(ks * 32 + aKB)) ^ aMask);
                ldsm_x4(a[mt][0], a[mt][1], a[mt][2], a[mt][3], addr);
            }
            #pragma unroll
            for (int nh = 0; nh < 2; nh++) {
                uint32_t addr = bB + (uint32_t)((bRow + nh * 16) * 128)
                              + (((uint32_t)(ks * 32 + bKB)) ^ bMask);
                ldsm_x4(bf[nh][0], bf[nh][1], bf[nh][2], bf[nh][3], addr);
            }
            #pragma unroll
            for (int mt = 0; mt < 4; mt++)
                #pragma unroll
                for (int nt = 0; nt < 4; nt++)
                    mma_f16acc(acc[mt][nt], a[mt],
                               bf[nt >> 1][(nt & 1) * 2],
                               bf[nt >> 1][(nt & 1) * 2 + 1]);
        }
        __syncthreads();
    }

    // ---- epilogue: L2 -> 5-kernel RBF sum ----
    float m = g_m;
    int rbase = wm + (lane >> 2);
    int cbase = wn + ((lane & 3) << 1);
    int rglob = ti * TILE, cglob = tj * TILE;
    float total = 0.f;
    #pragma unroll
    for (int mt = 0; mt < 4; mt++) {
        int rr = rbase + mt * 16;
        #pragma unroll
        for (int nt = 0; nt < 4; nt++) {
            int cc = cbase + nt * 8;
            float sb0 = sqcol[cc], sb1 = sqcol[cc + 1];
            #pragma unroll
            for (int e2 = 0; e2 < 2; e2++) {
                int rl = rr + e2 * 8;
                float sa = sqrow[rl];
                float2 dv = __half22float2(*(const half2*)&acc[mt][nt][e2]);
                float L2a = fmaxf(sa + sb0 - 2.f * dv.x, 0.f);
                float L2b = fmaxf(sa + sb1 - 2.f * dv.y, 0.f);
                float ea, eb;
                asm("ex2.approx.ftz.f32 %0, %1;" : "=f"(ea) : "f"(-L2a * m));
                asm("ex2.approx.ftz.f32 %0, %1;" : "=f"(eb) : "f"(-L2b * m));
                float ea1 = ea * ea, ea2 = ea1 * ea1, ea3 = ea2 * ea2, ea4 = ea3 * ea3;
                float eb1 = eb * eb, eb2 = eb1 * eb1, eb3 = eb2 * eb2, eb4 = eb3 * eb3;
                float kva = ((ea + ea1) + (ea2 + ea3)) + ea4;
                float kvb = ((eb + eb1) + (eb2 + eb3)) + eb4;
                int rg = rglob + rl, cg = cglob + cc;
                total += (rg > cg)     ? kva : 0.f;
                total += (rg > cg + 1) ? kvb : 0.f;
            }
        }
    }
    total *= (((ti < 32) == (tj < 32)) ? 2.f : -2.f);

    #pragma unroll
    for (int o = 16; o; o >>= 1) total += __shfl_xor_sync(0xffffffffu, total, o);
    float* red = (float*)(smem + RED_OFF);
    if (lane == 0) red[wid] = total;
    __syncthreads();
    if (tid == 0) {
        float s = 0.f;
        #pragma unroll
        for (int w = 0; w < 8; w++) s += red[w];
        atomicAdd(&g_acc, (double)s);
        __threadfence();
        if (atomicAdd(&g_cnt2, 1u) == (unsigned)NBLK - 1u) {
            out[0] = (float)((g_acc + (double)NTOT * 5.0) /
                             ((double)BHALF * (double)BHALF));
            g_cnt2 = 0u;
        }
    }
}

// ---------------- launch ----------------
extern "C" void kernel_launch(void* const* d_in, const int* in_sizes, int n_in,
                              void* d_out, int out_size) {
    const float* xs = (const float*)d_in[0];
    const float* xt = (const float*)d_in[1];
    float* out = (float*)d_out;

    cudaFuncSetAttribute(mmd_mma_kernel,
                         cudaFuncAttributeMaxDynamicSharedMemorySize, SMEM_TOTAL);

    convert_kernel<<<NCONV, 256>>>(xs, xt);
    mmd_mma_kernel<<<NBLK, NT, SMEM_TOTAL>>>(out);
}